// round 5
// baseline (speedup 1.0000x reference)
#include <cuda_runtime.h>
#include <cuda_bf16.h>
#include <cstdint>

#define BATCH 64
#define SEQ   512
#define DIM   1024
#define TAGS  32

__device__ float g_x[BATCH * SEQ * TAGS];
__device__ float g_logz[BATCH];
__device__ float g_score[BATCH];

// ---------------------------------------------------------------------------
// Kernel 1: emissions GEMM (unchanged — 29.6us known good).
// ---------------------------------------------------------------------------
__device__ __forceinline__ void mma_bf16(float& d0, float& d1, float& d2, float& d3,
                                         uint32_t a0, uint32_t a1, uint32_t a2, uint32_t a3,
                                         uint32_t b0, uint32_t b1) {
    asm volatile(
        "mma.sync.aligned.m16n8k16.row.col.f32.bf16.bf16.f32 "
        "{%0,%1,%2,%3}, {%4,%5,%6,%7}, {%8,%9}, {%0,%1,%2,%3};\n"
        : "+f"(d0), "+f"(d1), "+f"(d2), "+f"(d3)
        : "r"(a0), "r"(a1), "r"(a2), "r"(a3), "r"(b0), "r"(b1));
}

__device__ __forceinline__ uint32_t pack_bf16(float lo, float hi) {
    __nv_bfloat162 h = __floats2bfloat162_rn(lo, hi);
    return *reinterpret_cast<uint32_t*>(&h);
}

#define ASTRIDE 68
#define WSTRIDE 40

__global__ __launch_bounds__(256)
void emissions_gemm_kernel(const float* __restrict__ feat,
                           const float* __restrict__ Wg,
                           const float* __restrict__ bias,
                           float* __restrict__ xout) {
    __shared__ uint32_t Asm[64 * ASTRIDE];
    __shared__ uint32_t Wp [64 * WSTRIDE];

    const int tid  = threadIdx.x;
    const int lane = tid & 31;
    const int w    = tid >> 5;
    const int m0   = blockIdx.x * 64;

    float4 areg[8];
    float  wlo[8], whi[8];

#pragma unroll
    for (int i = 0; i < 8; i++) {
        const int idx = tid + i * 256;
        const int row = idx >> 5, kq = idx & 31;
        areg[i] = *reinterpret_cast<const float4*>(
            feat + (size_t)(m0 + row) * DIM + 4 * kq);
    }
#pragma unroll
    for (int i = 0; i < 8; i++) {
        const int idx = tid + i * 256;
        const int kp = idx >> 5, n = idx & 31;
        wlo[i] = Wg[(size_t)(2 * kp) * TAGS + n];
        whi[i] = Wg[(size_t)(2 * kp + 1) * TAGS + n];
    }

    float acc[2][4];
#pragma unroll
    for (int f = 0; f < 2; f++)
#pragma unroll
        for (int j = 0; j < 4; j++) acc[f][j] = 0.f;

    const int rb = (w & 3) * 16;
    const int nb = (w >> 2) * 16;
    const int g  = lane >> 2;
    const int t  = lane & 3;

    for (int c = 0; c < 8; c++) {
#pragma unroll
        for (int i = 0; i < 8; i++) {
            const int idx = tid + i * 256;
            const int row = idx >> 5, kq = idx & 31;
            Asm[row * ASTRIDE + 2 * kq]     = pack_bf16(areg[i].x, areg[i].y);
            Asm[row * ASTRIDE + 2 * kq + 1] = pack_bf16(areg[i].z, areg[i].w);
        }
#pragma unroll
        for (int i = 0; i < 8; i++) {
            const int idx = tid + i * 256;
            const int kp = idx >> 5, n = idx & 31;
            Wp[kp * WSTRIDE + n] = pack_bf16(wlo[i], whi[i]);
        }
        __syncthreads();

        if (c < 7) {
            const int kc = (c + 1) * 128;
#pragma unroll
            for (int i = 0; i < 8; i++) {
                const int idx = tid + i * 256;
                const int row = idx >> 5, kq = idx & 31;
                areg[i] = *reinterpret_cast<const float4*>(
                    feat + (size_t)(m0 + row) * DIM + kc + 4 * kq);
            }
#pragma unroll
            for (int i = 0; i < 8; i++) {
                const int idx = tid + i * 256;
                const int kp = idx >> 5, n = idx & 31;
                wlo[i] = Wg[(size_t)(kc + 2 * kp) * TAGS + n];
                whi[i] = Wg[(size_t)(kc + 2 * kp + 1) * TAGS + n];
            }
        }

#pragma unroll
        for (int kf = 0; kf < 8; kf++) {
            const int kw = 8 * kf;
            const uint32_t a0 = Asm[(rb + g)     * ASTRIDE + kw + t];
            const uint32_t a1 = Asm[(rb + g + 8) * ASTRIDE + kw + t];
            const uint32_t a2 = Asm[(rb + g)     * ASTRIDE + kw + 4 + t];
            const uint32_t a3 = Asm[(rb + g + 8) * ASTRIDE + kw + 4 + t];
#pragma unroll
            for (int f = 0; f < 2; f++) {
                const uint32_t b0 = Wp[(kw + t)     * WSTRIDE + nb + 8 * f + g];
                const uint32_t b1 = Wp[(kw + 4 + t) * WSTRIDE + nb + 8 * f + g];
                mma_bf16(acc[f][0], acc[f][1], acc[f][2], acc[f][3],
                         a0, a1, a2, a3, b0, b1);
            }
        }
        __syncthreads();
    }

    const int c2 = 2 * t;
    const int row0 = m0 + rb + g;
#pragma unroll
    for (int f = 0; f < 2; f++) {
        const int col = nb + 8 * f + c2;
        const float bv0 = bias[col], bv1 = bias[col + 1];
        *reinterpret_cast<float2*>(xout + (size_t)row0 * TAGS + col) =
            make_float2(acc[f][0] + bv0, acc[f][1] + bv1);
        *reinterpret_cast<float2*>(xout + (size_t)(row0 + 8) * TAGS + col) =
            make_float2(acc[f][2] + bv0, acc[f][3] + bv1);
    }
}

// ---------------------------------------------------------------------------
// Packed f32x2 helpers (sm_103a FFMA2 pipe, PTX-only).
// ---------------------------------------------------------------------------
__device__ __forceinline__ uint64_t pack2(float lo, float hi) {
    uint64_t r;
    asm("mov.b64 %0, {%1, %2};" : "=l"(r) : "f"(lo), "f"(hi));
    return r;
}
__device__ __forceinline__ void unpack2(float& lo, float& hi, uint64_t v) {
    asm("mov.b64 {%0, %1}, %2;" : "=f"(lo), "=f"(hi) : "l"(v));
}
#define FMA2(acc, a, b) \
    asm("fma.rn.f32x2 %0, %1, %2, %0;" : "+l"(acc) : "l"(a), "l"(b))
#define MUL2(dst, a, b) \
    asm("mul.rn.f32x2 %0, %1, %2;" : "=l"(dst) : "l"(a), "l"(b))
#define ADD2(dst, a, b) \
    asm("add.rn.f32x2 %0, %1, %2;" : "=l"(dst) : "l"(a), "l"(b))

// ---------------------------------------------------------------------------
// Kernel 2: fused CRF. Warp 0 = alpha recursion via smem ping-pong + packed
// f32x2 FMAs. Warp 1 = numerator score (parallel gathers).
// ---------------------------------------------------------------------------
__device__ __forceinline__ int tag_at(const int* __restrict__ tg, int idx, bool is64) {
    return is64 ? __ldg(tg + 2 * idx) : __ldg(tg + idx);
}

__global__ __launch_bounds__(64)
void crf_kernel(const int* __restrict__ tags,
                const float* __restrict__ start_t,
                const float* __restrict__ end_t,
                const float* __restrict__ trans) {
    __shared__ __align__(16) float ps[2][32];   // ping-pong alpha buffers

    const unsigned F = 0xffffffffu;
    const int lane = threadIdx.x & 31;
    const int warp = threadIdx.x >> 5;
    const int b = blockIdx.x;
    const int base = b * SEQ;

    // int64 vs int32 tag layout detection
    const int v1 = tags[2 * lane + 1];
    const int v2 = tags[2 * lane + 65];
    const bool okd = (v1 == 0 || v1 == -1) && (v2 == 0 || v2 == -1);
    const bool is64 = __all_sync(F, okd);

    const float* xrow = g_x + (size_t)b * SEQ * TAGS;

    if (warp == 1) {
        // ---------------- numerator score (order-parallel) ----------------
        int Tg[16];
#pragma unroll
        for (int k = 0; k < 16; k++)
            Tg[k] = tag_at(tags, base + k * 32 + lane, is64);

        int len = 0;
#pragma unroll
        for (int k = 0; k < 16; k++)
            len += __popc(__ballot_sync(F, Tg[k] != -1));

        float acc = 0.f;
        int carry = 0;
#pragma unroll
        for (int k = 0; k < 16; k++) {
            const int tt = k * 32 + lane;
            const int tg = Tg[k];
            const bool valid = tg >= 0;
            int tgp = __shfl_up_sync(F, tg, 1);
            if (lane == 0) tgp = carry;
            carry = __shfl_sync(F, Tg[k], 31);
            const int tgc = valid ? tg : 0;
            const int tgpc = tgp >= 0 ? tgp : 0;
            const float em = __ldg(xrow + tt * 32 + tgc);
            const float tr = (tt == 0) ? __ldg(start_t + tgc)
                                       : __ldg(trans + tgpc * 32 + tgc);
            float c = valid ? (tr + em) : 0.f;
            if (valid && tt == len - 1) c += __ldg(end_t + tgc);
            acc += c;
        }
#pragma unroll
        for (int off = 16; off > 0; off >>= 1)
            acc += __shfl_xor_sync(F, acc, off);
        if (lane == 0) g_score[b] = acc;
        return;
    }

    // ---------------- warp 0: alpha recursion -> logZ ----------------
    int len = 0;
#pragma unroll
    for (int k = 0; k < 16; k++) {
        const int tv = tag_at(tags, base + k * 32 + lane, is64);
        len += __popc(__ballot_sync(F, tv != -1));
    }

    // lane = destination tag column. Tc2[k] packs exp(trans[2k][lane]),
    // exp(trans[2k+1][lane]).
    uint64_t Tc2[16];
#pragma unroll
    for (int k = 0; k < 16; k++) {
        const float lo = __expf(__ldg(trans + (2 * k)     * 32 + lane));
        const float hi = __expf(__ldg(trans + (2 * k + 1) * 32 + lane));
        Tc2[k] = pack2(lo, hi);
    }
    const float st = __ldg(start_t + lane);
    const float en = __ldg(end_t + lane);

    float p = __expf(st + __ldg(xrow + lane));
    float C = 0.f;
    ps[0][lane] = p;

    // prefetch t = 1..8 (len >= 256 always)
    float E[8];
#pragma unroll
    for (int i = 0; i < 8; i++) E[i] = __ldg(xrow + (1 + i) * 32 + lane);

    // One step: packed dot of replicated p (smem, read as ulonglong2) with Tc2.
    // Accs: A0 <- u0.x,u2.x,u4.x,u6.x ; A1 <- u0.y,... ; A2 <- u1.x,... ; A3 <- u1.y,...
#define ALPHA_STEP(i, bp, DO_RENORM, VALID)                                    \
    {                                                                          \
        __syncwarp();                                                          \
        const ulonglong2* q = reinterpret_cast<const ulonglong2*>(&ps[bp][0]); \
        const ulonglong2 u0 = q[0], u1 = q[1], u2 = q[2], u3 = q[3];           \
        const ulonglong2 u4 = q[4], u5 = q[5], u6 = q[6], u7 = q[7];           \
        const float ee = __expf(E[i]);                                         \
        uint64_t A0, A1, A2, A3;                                               \
        MUL2(A0, u0.x, Tc2[0]);  MUL2(A1, u0.y, Tc2[1]);                       \
        MUL2(A2, u1.x, Tc2[2]);  MUL2(A3, u1.y, Tc2[3]);                       \
        FMA2(A0, u2.x, Tc2[4]);  FMA2(A1, u2.y, Tc2[5]);                       \
        FMA2(A2, u3.x, Tc2[6]);  FMA2(A3, u3.y, Tc2[7]);                       \
        FMA2(A0, u4.x, Tc2[8]);  FMA2(A1, u4.y, Tc2[9]);                       \
        FMA2(A2, u5.x, Tc2[10]); FMA2(A3, u5.y, Tc2[11]);                      \
        FMA2(A0, u6.x, Tc2[12]); FMA2(A1, u6.y, Tc2[13]);                      \
        FMA2(A2, u7.x, Tc2[14]); FMA2(A3, u7.y, Tc2[15]);                      \
        uint64_t B0, B1, B2;                                                   \
        ADD2(B0, A0, A1); ADD2(B1, A2, A3); ADD2(B2, B0, B1);                  \
        float slo, shi;                                                        \
        unpack2(slo, shi, B2);                                                 \
        float pn = (slo + shi) * ee;                                           \
        if (DO_RENORM) {                                                       \
            float m0lo, m0hi;                                                  \
            unpack2(m0lo, m0hi, u0.x);                                         \
            float inv;                                                         \
            asm("rcp.approx.f32 %0, %1;" : "=f"(inv) : "f"(m0lo));             \
            pn *= inv;                                                         \
            C += __logf(m0lo);                                                 \
        }                                                                      \
        p = (VALID) ? pn : p;                                                  \
        ps[bp ^ 1][lane] = p;                                                  \
    }

    int t = 1;
    int bp = 0;
    while (t + 8 <= len) {
        // 8 steps; renorm at i=3 and i=7 (same schedule as the passing R4)
        ALPHA_STEP(0, bp, false, true); bp ^= 1;
        {   const int tn = t + 8;  const bool okn = tn < len;
            E[0] = okn ? __ldg(xrow + tn * 32 + lane) : 0.f; }
        ALPHA_STEP(1, bp, false, true); bp ^= 1;
        {   const int tn = t + 9;  const bool okn = tn < len;
            E[1] = okn ? __ldg(xrow + tn * 32 + lane) : 0.f; }
        ALPHA_STEP(2, bp, false, true); bp ^= 1;
        {   const int tn = t + 10; const bool okn = tn < len;
            E[2] = okn ? __ldg(xrow + tn * 32 + lane) : 0.f; }
        ALPHA_STEP(3, bp, true, true);  bp ^= 1;
        {   const int tn = t + 11; const bool okn = tn < len;
            E[3] = okn ? __ldg(xrow + tn * 32 + lane) : 0.f; }
        ALPHA_STEP(4, bp, false, true); bp ^= 1;
        {   const int tn = t + 12; const bool okn = tn < len;
            E[4] = okn ? __ldg(xrow + tn * 32 + lane) : 0.f; }
        ALPHA_STEP(5, bp, false, true); bp ^= 1;
        {   const int tn = t + 13; const bool okn = tn < len;
            E[5] = okn ? __ldg(xrow + tn * 32 + lane) : 0.f; }
        ALPHA_STEP(6, bp, false, true); bp ^= 1;
        {   const int tn = t + 14; const bool okn = tn < len;
            E[6] = okn ? __ldg(xrow + tn * 32 + lane) : 0.f; }
        ALPHA_STEP(7, bp, true, true);  bp ^= 1;
        {   const int tn = t + 15; const bool okn = tn < len;
            E[7] = okn ? __ldg(xrow + tn * 32 + lane) : 0.f; }
        t += 8;
    }
    // masked epilogue (<= 7 steps, no renorm; bounded growth is safe in fp32)
#pragma unroll
    for (int i = 0; i < 7; i++) {
        const bool valid = (t + i) < len;
        ALPHA_STEP(i, bp, false, valid); bp ^= 1;
    }
#undef ALPHA_STEP

    float v = p * __expf(en);
#pragma unroll
    for (int off = 16; off > 0; off >>= 1) v += __shfl_xor_sync(F, v, off);
    if (lane == 0) g_logz[b] = C + __logf(v);
}

// ---------------------------------------------------------------------------
// Kernel 3: out = -mean(score - logz)
// ---------------------------------------------------------------------------
__global__ void finish_kernel(float* __restrict__ out) {
    const int lane = threadIdx.x;
    float v = (g_score[lane] - g_logz[lane]) +
              (g_score[lane + 32] - g_logz[lane + 32]);
#pragma unroll
    for (int off = 16; off > 0; off >>= 1) v += __shfl_xor_sync(0xffffffffu, v, off);
    if (lane == 0) out[0] = -v * (1.0f / (float)BATCH);
}

// ---------------------------------------------------------------------------
extern "C" void kernel_launch(void* const* d_in, const int* in_sizes, int n_in,
                              void* d_out, int out_size) {
    const float* feat    = (const float*)d_in[0];
    const int*   tags    = (const int*)  d_in[1];
    const float* W       = (const float*)d_in[2];
    const float* bias    = (const float*)d_in[3];
    const float* start_t = (const float*)d_in[4];
    const float* end_t   = (const float*)d_in[5];
    const float* trans   = (const float*)d_in[6];
    float* out = (float*)d_out;

    float* xg = nullptr;
    cudaGetSymbolAddress((void**)&xg, g_x);

    emissions_gemm_kernel<<<(BATCH * SEQ) / 64, 256>>>(feat, W, bias, xg);
    crf_kernel<<<BATCH, 64>>>(tags, start_t, end_t, trans);
    finish_kernel<<<1, 32>>>(out);
}

// round 6
// speedup vs baseline: 1.2996x; 1.2996x over previous
#include <cuda_runtime.h>
#include <cuda_bf16.h>
#include <cstdint>

#define BATCH 64
#define SEQ   512
#define DIM   1024
#define TAGS  32

__device__ float g_x[BATCH * SEQ * TAGS];
__device__ float g_logz[BATCH];
__device__ float g_score[BATCH];
__device__ int   g_flag[BATCH * 8];     // per (batch, 64-step chunk) release flag

// ---------------------------------------------------------------------------
// mma helpers (GEMM identical math to the 29.6us known-good version)
// ---------------------------------------------------------------------------
__device__ __forceinline__ void mma_bf16(float& d0, float& d1, float& d2, float& d3,
                                         uint32_t a0, uint32_t a1, uint32_t a2, uint32_t a3,
                                         uint32_t b0, uint32_t b1) {
    asm volatile(
        "mma.sync.aligned.m16n8k16.row.col.f32.bf16.bf16.f32 "
        "{%0,%1,%2,%3}, {%4,%5,%6,%7}, {%8,%9}, {%0,%1,%2,%3};\n"
        : "+f"(d0), "+f"(d1), "+f"(d2), "+f"(d3)
        : "r"(a0), "r"(a1), "r"(a2), "r"(a3), "r"(b0), "r"(b1));
}

__device__ __forceinline__ uint32_t pack_bf16(float lo, float hi) {
    __nv_bfloat162 h = __floats2bfloat162_rn(lo, hi);
    return *reinterpret_cast<uint32_t*>(&h);
}

__device__ __forceinline__ void wait_flag(const int* f) {
    int v;
    do {
        asm volatile("ld.global.acquire.gpu.b32 %0, [%1];"
                     : "=r"(v) : "l"(f) : "memory");
        if (!v) __nanosleep(64);
    } while (!v);
}

__device__ __forceinline__ int tag_at(const int* __restrict__ tg, int idx, bool is64) {
    return is64 ? __ldg(tg + 2 * idx) : __ldg(tg + idx);
}

#define ASTRIDE 68
#define WSTRIDE 40
#define NCRF 64   // CRF blocks come first in the grid

// ---------------------------------------------------------------------------
// Fused kernel: blocks [0,64) = CRF consumer (2 active warps);
//               blocks [64,576) = GEMM producer (8 warps).
// ---------------------------------------------------------------------------
__global__ __launch_bounds__(256)
void fused_kernel(const float* __restrict__ feat,
                  const int*   __restrict__ tags,
                  const float* __restrict__ Wg,
                  const float* __restrict__ bias,
                  const float* __restrict__ start_t,
                  const float* __restrict__ end_t,
                  const float* __restrict__ trans) {
    if (blockIdx.x >= NCRF) {
        // ==================== GEMM producer ====================
        __shared__ uint32_t Asm[64 * ASTRIDE];
        __shared__ uint32_t Wp [64 * WSTRIDE];

        const int tid  = threadIdx.x;
        const int lane = tid & 31;
        const int w    = tid >> 5;
        const int m0   = (blockIdx.x - NCRF) * 64;

        float4 areg[8];
        float  wlo[8], whi[8];

#pragma unroll
        for (int i = 0; i < 8; i++) {
            const int idx = tid + i * 256;
            const int row = idx >> 5, kq = idx & 31;
            areg[i] = *reinterpret_cast<const float4*>(
                feat + (size_t)(m0 + row) * DIM + 4 * kq);
        }
#pragma unroll
        for (int i = 0; i < 8; i++) {
            const int idx = tid + i * 256;
            const int kp = idx >> 5, n = idx & 31;
            wlo[i] = Wg[(size_t)(2 * kp) * TAGS + n];
            whi[i] = Wg[(size_t)(2 * kp + 1) * TAGS + n];
        }

        float acc[2][4];
#pragma unroll
        for (int f = 0; f < 2; f++)
#pragma unroll
            for (int j = 0; j < 4; j++) acc[f][j] = 0.f;

        const int rb = (w & 3) * 16;
        const int nb = (w >> 2) * 16;
        const int g  = lane >> 2;
        const int t  = lane & 3;

        for (int c = 0; c < 8; c++) {
#pragma unroll
            for (int i = 0; i < 8; i++) {
                const int idx = tid + i * 256;
                const int row = idx >> 5, kq = idx & 31;
                Asm[row * ASTRIDE + 2 * kq]     = pack_bf16(areg[i].x, areg[i].y);
                Asm[row * ASTRIDE + 2 * kq + 1] = pack_bf16(areg[i].z, areg[i].w);
            }
#pragma unroll
            for (int i = 0; i < 8; i++) {
                const int idx = tid + i * 256;
                const int kp = idx >> 5, n = idx & 31;
                Wp[kp * WSTRIDE + n] = pack_bf16(wlo[i], whi[i]);
            }
            __syncthreads();

            if (c < 7) {
                const int kc = (c + 1) * 128;
#pragma unroll
                for (int i = 0; i < 8; i++) {
                    const int idx = tid + i * 256;
                    const int row = idx >> 5, kq = idx & 31;
                    areg[i] = *reinterpret_cast<const float4*>(
                        feat + (size_t)(m0 + row) * DIM + kc + 4 * kq);
                }
#pragma unroll
                for (int i = 0; i < 8; i++) {
                    const int idx = tid + i * 256;
                    const int kp = idx >> 5, n = idx & 31;
                    wlo[i] = Wg[(size_t)(kc + 2 * kp) * TAGS + n];
                    whi[i] = Wg[(size_t)(kc + 2 * kp + 1) * TAGS + n];
                }
            }

#pragma unroll
            for (int kf = 0; kf < 8; kf++) {
                const int kw = 8 * kf;
                const uint32_t a0 = Asm[(rb + g)     * ASTRIDE + kw + t];
                const uint32_t a1 = Asm[(rb + g + 8) * ASTRIDE + kw + t];
                const uint32_t a2 = Asm[(rb + g)     * ASTRIDE + kw + 4 + t];
                const uint32_t a3 = Asm[(rb + g + 8) * ASTRIDE + kw + 4 + t];
#pragma unroll
                for (int f = 0; f < 2; f++) {
                    const uint32_t b0 = Wp[(kw + t)     * WSTRIDE + nb + 8 * f + g];
                    const uint32_t b1 = Wp[(kw + 4 + t) * WSTRIDE + nb + 8 * f + g];
                    mma_bf16(acc[f][0], acc[f][1], acc[f][2], acc[f][3],
                             a0, a1, a2, a3, b0, b1);
                }
            }
            __syncthreads();
        }

        const int c2 = 2 * t;
        const int row0 = m0 + rb + g;
#pragma unroll
        for (int f = 0; f < 2; f++) {
            const int col = nb + 8 * f + c2;
            const float bv0 = bias[col], bv1 = bias[col + 1];
            *reinterpret_cast<float2*>(g_x + (size_t)row0 * TAGS + col) =
                make_float2(acc[f][0] + bv0, acc[f][1] + bv1);
            *reinterpret_cast<float2*>(g_x + (size_t)(row0 + 8) * TAGS + col) =
                make_float2(acc[f][2] + bv0, acc[f][3] + bv1);
        }

        // release this (batch, chunk)
        __threadfence();
        __syncthreads();
        if (tid == 0) {
            const int fb = m0 >> 9;          // batch
            const int fc = (m0 >> 6) & 7;    // 64-step chunk within batch
            atomicExch(&g_flag[fb * 8 + fc], 1);
        }
        return;
    }

    // ==================== CRF consumer ====================
    const unsigned F = 0xffffffffu;
    const int tid  = threadIdx.x;
    const int lane = tid & 31;
    const int warp = tid >> 5;
    const int b = blockIdx.x;
    const int base = b * SEQ;
    const float* xrow = g_x + (size_t)b * SEQ * TAGS;
    int* flags = &g_flag[b * 8];

    __shared__ __align__(16) float ps[2][32];

    if (warp < 2) {
        // tag dtype detection
        const int v1 = tags[2 * lane + 1];
        const int v2 = tags[2 * lane + 65];
        const bool okd = (v1 == 0 || v1 == -1) && (v2 == 0 || v2 == -1);
        const bool is64 = __all_sync(F, okd);

        if (warp == 1) {
            // ---------- numerator score (order-parallel gathers) ----------
            int Tg[16];
#pragma unroll
            for (int k = 0; k < 16; k++)
                Tg[k] = tag_at(tags, base + k * 32 + lane, is64);

            int len = 0;
#pragma unroll
            for (int k = 0; k < 16; k++)
                len += __popc(__ballot_sync(F, Tg[k] != -1));

            // wait for the whole batch's emissions
            if (lane < 8) wait_flag(&flags[lane]);
            __syncwarp();

            float acc = 0.f;
            int carry = 0;
#pragma unroll
            for (int k = 0; k < 16; k++) {
                const int tt = k * 32 + lane;
                const int tg = Tg[k];
                const bool valid = tg >= 0;
                int tgp = __shfl_up_sync(F, tg, 1);
                if (lane == 0) tgp = carry;
                carry = __shfl_sync(F, Tg[k], 31);
                const int tgc = valid ? tg : 0;
                const int tgpc = tgp >= 0 ? tgp : 0;
                const float em = xrow[tt * 32 + tgc];
                const float tr = (tt == 0) ? __ldg(start_t + tgc)
                                           : __ldg(trans + tgpc * 32 + tgc);
                float c = valid ? (tr + em) : 0.f;
                if (valid && tt == len - 1) c += __ldg(end_t + tgc);
                acc += c;
            }
#pragma unroll
            for (int off = 16; off > 0; off >>= 1)
                acc += __shfl_xor_sync(F, acc, off);
            if (lane == 0) g_score[b] = acc;
        } else {
            // ---------- alpha recursion -> logZ (R4 scalar form) ----------
            int len = 0;
#pragma unroll
            for (int k = 0; k < 16; k++) {
                const int tv = tag_at(tags, base + k * 32 + lane, is64);
                len += __popc(__ballot_sync(F, tv != -1));
            }

            float Tc[32];
#pragma unroll
            for (int i = 0; i < 32; i++)
                Tc[i] = __expf(__ldg(trans + i * 32 + lane));
            const float st = __ldg(start_t + lane);
            const float en = __ldg(end_t + lane);

            // chunk 0 must be ready before we touch xrow
            wait_flag(&flags[0]);
            int last_ready = 0;

            float p = __expf(st + xrow[lane]);
            float C = 0.f;
            ps[0][lane] = p;

            float E[8];
#pragma unroll
            for (int i = 0; i < 8; i++) E[i] = xrow[(1 + i) * 32 + lane];

#define ALPHA_STEP(i, bp, DO_RENORM, VALID)                                    \
    {                                                                          \
        __syncwarp();                                                          \
        float4 q0 = *reinterpret_cast<const float4*>(&ps[bp][0]);              \
        float4 q1 = *reinterpret_cast<const float4*>(&ps[bp][4]);              \
        float4 q2 = *reinterpret_cast<const float4*>(&ps[bp][8]);              \
        float4 q3 = *reinterpret_cast<const float4*>(&ps[bp][12]);             \
        float4 q4 = *reinterpret_cast<const float4*>(&ps[bp][16]);             \
        float4 q5 = *reinterpret_cast<const float4*>(&ps[bp][20]);             \
        float4 q6 = *reinterpret_cast<const float4*>(&ps[bp][24]);             \
        float4 q7 = *reinterpret_cast<const float4*>(&ps[bp][28]);             \
        const float ee = __expf(E[i]);                                         \
        float s0 = q0.x * Tc[0],  s1 = q0.y * Tc[1];                           \
        float s2 = q0.z * Tc[2],  s3 = q0.w * Tc[3];                           \
        s0 = fmaf(q1.x, Tc[4],  s0); s1 = fmaf(q1.y, Tc[5],  s1);              \
        s2 = fmaf(q1.z, Tc[6],  s2); s3 = fmaf(q1.w, Tc[7],  s3);              \
        s0 = fmaf(q2.x, Tc[8],  s0); s1 = fmaf(q2.y, Tc[9],  s1);              \
        s2 = fmaf(q2.z, Tc[10], s2); s3 = fmaf(q2.w, Tc[11], s3);              \
        s0 = fmaf(q3.x, Tc[12], s0); s1 = fmaf(q3.y, Tc[13], s1);              \
        s2 = fmaf(q3.z, Tc[14], s2); s3 = fmaf(q3.w, Tc[15], s3);              \
        s0 = fmaf(q4.x, Tc[16], s0); s1 = fmaf(q4.y, Tc[17], s1);              \
        s2 = fmaf(q4.z, Tc[18], s2); s3 = fmaf(q4.w, Tc[19], s3);              \
        s0 = fmaf(q5.x, Tc[20], s0); s1 = fmaf(q5.y, Tc[21], s1);              \
        s2 = fmaf(q5.z, Tc[22], s2); s3 = fmaf(q5.w, Tc[23], s3);              \
        s0 = fmaf(q6.x, Tc[24], s0); s1 = fmaf(q6.y, Tc[25], s1);              \
        s2 = fmaf(q6.z, Tc[26], s2); s3 = fmaf(q6.w, Tc[27], s3);              \
        s0 = fmaf(q7.x, Tc[28], s0); s1 = fmaf(q7.y, Tc[29], s1);              \
        s2 = fmaf(q7.z, Tc[30], s2); s3 = fmaf(q7.w, Tc[31], s3);              \
        float pn = ((s0 + s1) + (s2 + s3)) * ee;                               \
        if (DO_RENORM) {                                                       \
            const float m = q0.x;                                              \
            float inv;                                                         \
            asm("rcp.approx.f32 %0, %1;" : "=f"(inv) : "f"(m));                \
            pn *= inv;                                                         \
            C += __logf(m);                                                    \
        }                                                                      \
        p = (VALID) ? pn : p;                                                  \
        ps[bp ^ 1][lane] = p;                                                  \
    }

            int t = 1;
            int bp = 0;
            while (t + 8 <= len) {
                // gate prefetch window [t+8, t+15]
                int need = (t + 15) >> 6;
                if (need > 7) need = 7;
                while (last_ready < need) {
                    last_ready++;
                    wait_flag(&flags[last_ready]);
                }

                ALPHA_STEP(0, bp, false, true); bp ^= 1;
                {   const int tn = t + 8;  const bool okn = tn < len;
                    E[0] = okn ? xrow[tn * 32 + lane] : 0.f; }
                ALPHA_STEP(1, bp, false, true); bp ^= 1;
                {   const int tn = t + 9;  const bool okn = tn < len;
                    E[1] = okn ? xrow[tn * 32 + lane] : 0.f; }
                ALPHA_STEP(2, bp, false, true); bp ^= 1;
                {   const int tn = t + 10; const bool okn = tn < len;
                    E[2] = okn ? xrow[tn * 32 + lane] : 0.f; }
                ALPHA_STEP(3, bp, true, true);  bp ^= 1;
                {   const int tn = t + 11; const bool okn = tn < len;
                    E[3] = okn ? xrow[tn * 32 + lane] : 0.f; }
                ALPHA_STEP(4, bp, false, true); bp ^= 1;
                {   const int tn = t + 12; const bool okn = tn < len;
                    E[4] = okn ? xrow[tn * 32 + lane] : 0.f; }
                ALPHA_STEP(5, bp, false, true); bp ^= 1;
                {   const int tn = t + 13; const bool okn = tn < len;
                    E[5] = okn ? xrow[tn * 32 + lane] : 0.f; }
                ALPHA_STEP(6, bp, false, true); bp ^= 1;
                {   const int tn = t + 14; const bool okn = tn < len;
                    E[6] = okn ? xrow[tn * 32 + lane] : 0.f; }
                ALPHA_STEP(7, bp, true, true);  bp ^= 1;
                {   const int tn = t + 15; const bool okn = tn < len;
                    E[7] = okn ? xrow[tn * 32 + lane] : 0.f; }
                t += 8;
            }
#pragma unroll
            for (int i = 0; i < 7; i++) {
                const bool valid = (t + i) < len;
                ALPHA_STEP(i, bp, false, valid); bp ^= 1;
            }
#undef ALPHA_STEP

            float v = p * __expf(en);
#pragma unroll
            for (int off = 16; off > 0; off >>= 1)
                v += __shfl_xor_sync(F, v, off);
            if (lane == 0) g_logz[b] = C + __logf(v);
        }
    }

    // reset flags for the next graph replay (after both warps are done;
    // warp 1 has verified all 8 flags were set)
    __syncthreads();
    if (tid < 8) flags[tid] = 0;
}

// ---------------------------------------------------------------------------
// finish: out = -mean(score - logz)
// ---------------------------------------------------------------------------
__global__ void finish_kernel(float* __restrict__ out) {
    const int lane = threadIdx.x;
    float v = (g_score[lane] - g_logz[lane]) +
              (g_score[lane + 32] - g_logz[lane + 32]);
#pragma unroll
    for (int off = 16; off > 0; off >>= 1) v += __shfl_xor_sync(0xffffffffu, v, off);
    if (lane == 0) out[0] = -v * (1.0f / (float)BATCH);
}

// ---------------------------------------------------------------------------
extern "C" void kernel_launch(void* const* d_in, const int* in_sizes, int n_in,
                              void* d_out, int out_size) {
    const float* feat    = (const float*)d_in[0];
    const int*   tags    = (const int*)  d_in[1];
    const float* W       = (const float*)d_in[2];
    const float* bias    = (const float*)d_in[3];
    const float* start_t = (const float*)d_in[4];
    const float* end_t   = (const float*)d_in[5];
    const float* trans   = (const float*)d_in[6];
    float* out = (float*)d_out;

    fused_kernel<<<NCRF + (BATCH * SEQ) / 64, 256>>>(
        feat, tags, W, bias, start_t, end_t, trans);
    finish_kernel<<<1, 32>>>(out);
}